// round 15
// baseline (speedup 1.0000x reference)
#include <cuda_runtime.h>
#include <math.h>
#include <stdint.h>

// Problem constants
#define BB  2
#define SS  4096
#define DDIM 1024
#define HH  16
#define DHH 64
#define MM  (BB*SS)   // 8192 rows

// Scratch (allocation-free rule: __device__ globals)
__device__ float g_x[MM*DDIM];                 // tf32-rounded x
__device__ float g_Wt[4u*DDIM*DDIM];           // tf32-rounded W^T (q,k,v,o)
__device__ float g_Q[MM*DDIM];                 // tf32-rounded q
__device__ float g_K[MM*DDIM];                 // tf32-rounded k (natural row-major)
__device__ float g_V[MM*DDIM];                 // tf32-rounded V TRANSPOSED: [b][h][d][s]
__device__ float g_ctx[MM*DDIM];               // tf32-rounded ctx

__device__ __forceinline__ float rna_tf32(float x) {
    uint32_t u;
    asm("cvt.rna.tf32.f32 %0, %1;" : "=r"(u) : "f"(x));
    return __uint_as_float(u);
}

__device__ __forceinline__ uint32_t smem_u32(const void* p) {
    uint32_t a;
    asm("{ .reg .u64 t; cvta.to.shared.u64 t, %1; cvt.u32.u64 %0, t; }"
        : "=r"(a) : "l"(p));
    return a;
}

__device__ __forceinline__ void cp_async16(uint32_t dst, const void* src) {
    asm volatile("cp.async.cg.shared.global [%0], [%1], 16;"
                 :: "r"(dst), "l"(src) : "memory");
}
#define CP_COMMIT() asm volatile("cp.async.commit_group;" ::: "memory")

#define MMA_TF32(c, a0, a1, a2, a3, b0, b1)                                    \
    asm volatile(                                                              \
        "mma.sync.aligned.m16n8k8.row.col.f32.tf32.tf32.f32 "                  \
        "{%0,%1,%2,%3},{%4,%5,%6,%7},{%8,%9},{%0,%1,%2,%3};"                   \
        : "+f"((c)[0]), "+f"((c)[1]), "+f"((c)[2]), "+f"((c)[3])               \
        : "r"(a0), "r"(a1), "r"(a2), "r"(a3), "r"(b0), "r"(b1))

#define LDSM_X4(r0, r1, r2, r3, addr)                                          \
    asm volatile("ldmatrix.sync.aligned.m8n8.x4.shared.b16 {%0,%1,%2,%3}, [%4];" \
                 : "=r"(r0), "=r"(r1), "=r"(r2), "=r"(r3) : "r"(addr))

#define LDSM_X2(r0, r1, addr)                                                  \
    asm volatile("ldmatrix.sync.aligned.m8n8.x2.shared.b16 {%0,%1}, [%2];"     \
                 : "=r"(r0), "=r"(r1) : "r"(addr))

// ===========================================================================
// Pre-pass kernels: tf32 RNA rounding of x; round+transpose for weights
// ===========================================================================
__global__ __launch_bounds__(256) void round_x_kernel(const float* __restrict__ x)
{
    const size_t i = ((size_t)blockIdx.x * 256 + threadIdx.x) * 4;
    float4 v = *(const float4*)(x + i);
    v.x = rna_tf32(v.x); v.y = rna_tf32(v.y);
    v.z = rna_tf32(v.z); v.w = rna_tf32(v.w);
    *(float4*)(g_x + i) = v;
}

__global__ __launch_bounds__(256) void transpose_round_kernel(
    const float* __restrict__ Wq, const float* __restrict__ Wk,
    const float* __restrict__ Wv, const float* __restrict__ Wo)
{
    __shared__ float t[32][33];
    const int z = blockIdx.z;
    const float* W = (z == 0) ? Wq : (z == 1) ? Wk : (z == 2) ? Wv : Wo;
    float* Wt = g_Wt + (size_t)z * DDIM * DDIM;
    const int x0 = blockIdx.x * 32, y0 = blockIdx.y * 32;
    const int tx = threadIdx.x, ty = threadIdx.y;   // block (32,8)
#pragma unroll
    for (int i = 0; i < 4; i++) {
        const int row = ty + i * 8;
        t[row][tx] = W[(size_t)(y0 + row) * DDIM + x0 + tx];
    }
    __syncthreads();
#pragma unroll
    for (int i = 0; i < 4; i++) {
        const int row = ty + i * 8;
        Wt[(size_t)(x0 + row) * DDIM + y0 + tx] = rna_tf32(t[tx][row]);
    }
}

// ===========================================================================
// tf32 mma.sync GEMM v2: C[8192,1024] = A @ Bt^T, CTA 128x128, BK=32.
// cp.async direct staging + ldmatrix fragment loads. 2 CTAs/SM.
// v_trans: output written TRANSPOSED to [b][h][d][s] (natural s) for g_V.
// ===========================================================================
#define GTM 128
#define GTN 128
#define GTK 32
#define GSTG_F 8192                            // A 4096 + B 4096 floats = 32KB
#define GEMM_SMEM_BYTES (3 * GSTG_F * 4)       // 98304; x2 CTAs = 192KB

__device__ __forceinline__ void gemm_mma_body(const float* __restrict__ A,
                                              const float* __restrict__ Bt,
                                              float* __restrict__ C,
                                              const float* __restrict__ bias,
                                              bool round_out, bool v_trans)
{
    extern __shared__ float sm[];
    const uint32_t sbase = smem_u32(sm);
    const int tid  = threadIdx.x;
    const int lane = tid & 31;
    const int warp = tid >> 5;
    const int wm   = warp >> 2;          // 0..1
    const int wn   = warp & 3;           // 0..3
    const int m0   = blockIdx.y * GTM;
    const int n0   = blockIdx.x * GTN;

    // ldmatrix per-lane constants
    const int aro = lane & 15;
    const int akx = lane >> 4;
    const int bro = lane & 7;
    const int bkx = (lane >> 3) & 1;
    const int l7  = lane & 7;

    float acc[16][4];
#pragma unroll
    for (int t = 0; t < 16; t++)
#pragma unroll
        for (int e = 0; e < 4; e++) acc[t][e] = 0.f;

#define G_ISSUE(it, s)                                                          \
    {                                                                           \
        const int kc = (it) * GTK;                                              \
        const uint32_t st = sbase + (uint32_t)(s) * (GSTG_F * 4);               \
        _Pragma("unroll")                                                       \
        for (int t = 0; t < 4; t++) {                                           \
            const int ch = tid + t * 256;                                       \
            const int row = ch >> 3, ck = ch & 7;                               \
            const uint32_t doff = row * 128 + ((ck ^ (row & 7)) << 4);          \
            cp_async16(st + doff, A  + (size_t)(m0 + row) * DDIM + kc + ck * 4);\
            cp_async16(st + 16384 + doff,                                       \
                       Bt + (size_t)(n0 + row) * DDIM + kc + ck * 4);           \
        }                                                                       \
        CP_COMMIT();                                                            \
    }

    G_ISSUE(0, 0);
    G_ISSUE(1, 1);

    for (int it = 0; it < 32; ++it) {
        if (it < 31) asm volatile("cp.async.wait_group 1;" ::: "memory");
        else         asm volatile("cp.async.wait_group 0;" ::: "memory");
        __syncthreads();

        const uint32_t sA = sbase + (uint32_t)(it % 3) * (GSTG_F * 4);
        const uint32_t sB = sA + 16384;

#pragma unroll
        for (int ks = 0; ks < 4; ks++) {
            const uint32_t aoff = (uint32_t)(((2 * ks + akx) ^ l7) << 4);
            const uint32_t boff = (uint32_t)(((2 * ks + bkx) ^ l7) << 4);
            uint32_t af[4][4];
            uint32_t bf[4][2];
#pragma unroll
            for (int i = 0; i < 4; i++) {
                const uint32_t addr = sA + (wm * 64 + i * 16 + aro) * 128 + aoff;
                LDSM_X4(af[i][0], af[i][1], af[i][2], af[i][3], addr);
            }
#pragma unroll
            for (int j = 0; j < 4; j++) {
                const uint32_t addr = sB + (wn * 32 + j * 8 + bro) * 128 + boff;
                LDSM_X2(bf[j][0], bf[j][1], addr);
            }
#pragma unroll
            for (int i = 0; i < 4; i++)
#pragma unroll
                for (int j = 0; j < 4; j++)
                    MMA_TF32(acc[i * 4 + j],
                             af[i][0], af[i][1], af[i][2], af[i][3],
                             bf[j][0], bf[j][1]);
        }

        __syncthreads();
        if (it + 2 < 32) G_ISSUE(it + 2, (it + 2) % 3);
    }

    const int g   = lane >> 2;
    const int cth = lane & 3;
#pragma unroll
    for (int i = 0; i < 4; i++) {
        const int row = m0 + wm * 64 + i * 16 + g;
#pragma unroll
        for (int j = 0; j < 4; j++) {
            const int col = n0 + wn * 32 + j * 8 + cth * 2;
            float2 v0 = make_float2(acc[i * 4 + j][0], acc[i * 4 + j][1]);
            float2 v1 = make_float2(acc[i * 4 + j][2], acc[i * 4 + j][3]);
            if (bias != nullptr) {
                const float b0 = bias[col], b1 = bias[col + 1];
                v0.x += b0; v0.y += b1;
                v1.x += b0; v1.y += b1;
            }
            if (round_out) {
                v0.x = rna_tf32(v0.x); v0.y = rna_tf32(v0.y);
                v1.x = rna_tf32(v1.x); v1.y = rna_tf32(v1.y);
            }
            if (v_trans) {
                // Vt[((b*16+h)*64 + d)][s], natural s
                const int b_ = row >> 12, srow = row & 4095;
                const int h_ = col >> 6, d0 = col & 63;
                float* vt = C + ((size_t)((b_ * HH + h_) * DHH + d0)) * SS;
                vt[srow]          = v0.x;
                vt[SS + srow]     = v0.y;   // d0+1
                vt[srow + 8]      = v1.x;   // row+8
                vt[SS + srow + 8] = v1.y;
            } else {
                *(float2*)&C[(size_t)row * DDIM + col]       = v0;
                *(float2*)&C[(size_t)(row + 8) * DDIM + col] = v1;
            }
        }
    }
#undef G_ISSUE
}

__global__ __launch_bounds__(256, 2) void qkv_mma_kernel()
{
    const float* Bt = g_Wt + (size_t)blockIdx.z * DDIM * DDIM;
    float* Cp = (blockIdx.z == 0) ? g_Q : (blockIdx.z == 1) ? g_K : g_V;
    gemm_mma_body(g_x, Bt, Cp, nullptr, true, blockIdx.z == 2);
}

__global__ __launch_bounds__(256, 2) void out_mma_kernel(const float* __restrict__ bo,
                                                         float* __restrict__ out)
{
    gemm_mma_body(g_ctx, g_Wt + 3ull * DDIM * DDIM, out, bo, false, false);
}

// ===========================================================================
// tf32 mma.sync causal flash attention.
// CTA: 128 queries x one (b,h), 256 threads (8 warps x 16 q-rows), 2 CTAs/SM.
// K staged row-major [key][d] stride 68; V staged TRANSPOSED [d][s] stride 68.
// B-fragments for BOTH mmas loaded via ldmatrix.x4: one instruction delivers
// (b0,b1) for TWO adjacent n-tiles (M0/M1 = nt0 k-halves, M2/M3 = nt1).
// Stride 68 => ldmatrix 8-row phases hit all 32 banks exactly once.
// Q A-frags in smem, scaled by 0.125*log2(e), rna'd after scaling.
// exp2-domain softmax.
// ===========================================================================
#define NEG_BIG   (-1e30f)
#define QK_SCALE  0.18033688f              // 0.125 * log2(e)
#define AT_STRIDE 68
#define AT_ROWB   (AT_STRIDE * 4)           // 272 bytes per staged row
#define AT_TILE_F (64 * AT_STRIDE)          // 4352 floats (17408 B)
#define AT_STAGE_F (2 * AT_TILE_F)          // K + V per stage = 8704 floats
#define QF_FLOATS 8192                      // 8 warps x 8 ks x 32 lanes x 4
#define ATT_SMEM_BYTES ((QF_FLOATS + 2 * AT_STAGE_F) * 4)   // 102400

__global__ __launch_bounds__(256, 2) void attn_mma_kernel()
{
    extern __shared__ float smf[];
    const uint32_t sb  = smem_u32(smf);
    const uint32_t kvb = sb + QF_FLOATS * 4;          // KV staging base
    float* kvf = smf + QF_FLOATS;
    const int tid = threadIdx.x, lane = tid & 31, warp = tid >> 5;
    const int bh = blockIdx.y, b = bh >> 4, h = bh & 15;
    const int qt = (int)gridDim.x - 1 - (int)blockIdx.x;   // heavy first
    const int q0 = qt * 128;
    const int qw0 = q0 + warp * 16;
    const int nb = 2 * qt + 2;
    const int r = lane >> 2, c = lane & 3;

    // ldmatrix x4 per-lane static offset: matrix = lane>>3 (M0..M3),
    // row-in-tile = lane&7; nt-offset (+8 rows) for M2/M3 via lane>>4;
    // k-chunk (+16B) for M1/M3 via (lane>>3)&1.
    const uint32_t lmo = (uint32_t)((((lane >> 4) * 8 + (lane & 7)) * AT_ROWB)
                                    + (((lane >> 3) & 1) << 4));

    const float* gq  = g_Q + (size_t)(b * SS + q0) * DDIM + h * DHH;
    const float* gk0 = g_K + (size_t)(b * SS) * DDIM + h * DHH;
    const float* gvt = g_V + (size_t)((b * HH + h) * DHH) * SS;   // [d][s]

    // ---- stage Q (128 x 64, stride 68) into KV region, build Q-frags ----
#pragma unroll
    for (int i = 0; i < 8; i++) {
        const int ch = tid + i * 256;
        const int row = ch >> 4, c16 = ch & 15;
        cp_async16(kvb + row * AT_ROWB + c16 * 16, gq + (size_t)row * DDIM + c16 * 4);
    }
    CP_COMMIT();
    asm volatile("cp.async.wait_group 0;" ::: "memory");
    __syncthreads();

    {
        float* qfw = smf + warp * 1024 + lane * 4;
#pragma unroll
        for (int ks = 0; ks < 8; ks++) {
            const float* qs = kvf + (warp * 16 + r) * AT_STRIDE + ks * 8 + c;
            float4 qv = make_float4(rna_tf32(qs[0] * QK_SCALE),
                                    rna_tf32(qs[8 * AT_STRIDE] * QK_SCALE),
                                    rna_tf32(qs[4] * QK_SCALE),
                                    rna_tf32(qs[8 * AT_STRIDE + 4] * QK_SCALE));
            *(float4*)&qfw[ks * 128] = qv;
        }
    }
    __syncthreads();

    float O[8][4];
#pragma unroll
    for (int t = 0; t < 8; t++)
#pragma unroll
        for (int e = 0; e < 4; e++) O[t][e] = 0.f;
    float m0v = NEG_BIG, m1v = NEG_BIG, l0v = 0.f, l1v = 0.f;

    // K tile rows = key; V tile rows = d (16 chunks of natural s each).
#define AT_ISSUE(kb, s)                                                            \
    {                                                                              \
        const float* gk = gk0 + (size_t)(kb) * 64 * DDIM;                          \
        const float* gv = gvt + (size_t)(kb) * 64;                                 \
        const uint32_t db = kvb + (uint32_t)(s) * (AT_STAGE_F * 4);                \
        _Pragma("unroll")                                                          \
        for (int i = 0; i < 4; i++) {                                              \
            const int ch = tid + i * 256;                                          \
            const int row = ch >> 4, c16 = ch & 15;                                \
            cp_async16(db + row * AT_ROWB + c16 * 16,                              \
                       gk + (size_t)row * DDIM + c16 * 4);                         \
            cp_async16(db + (AT_TILE_F * 4) + row * AT_ROWB + c16 * 16,            \
                       gv + (size_t)row * SS + c16 * 4);                           \
        }                                                                          \
    }

    AT_ISSUE(0, 0);
    CP_COMMIT();

    const int l0p = (lane & 28) | ((lane & 3) >> 1);
    const int l2p = l0p + 2;
    const bool odd = (lane & 1) != 0;
    const float* qfw = smf + warp * 1024 + lane * 4;

    for (int kb = 0; kb < nb; kb++) {
        if (kb + 1 < nb) {
            AT_ISSUE(kb + 1, (kb + 1) & 1);
            CP_COMMIT();
            asm volatile("cp.async.wait_group 1;" ::: "memory");
        } else {
            asm volatile("cp.async.wait_group 0;" ::: "memory");
        }
        __syncthreads();

        const int k0 = kb * 64;
        if (k0 <= qw0 + 15) {                       // else fully masked: skip
            const uint32_t Kad = kvb + (uint32_t)(kb & 1) * (AT_STAGE_F * 4) + lmo;
            const uint32_t Vad = Kad + (AT_TILE_F * 4);

            // ---- S = Q K^T : ldmatrix.x4 = B-frags for 2 n-tiles ----
            float s[8][4];
#pragma unroll
            for (int t = 0; t < 8; t++)
#pragma unroll
                for (int e = 0; e < 4; e++) s[t][e] = 0.f;

#pragma unroll
            for (int ks = 0; ks < 8; ks++) {
                const float4 qv = *(const float4*)&qfw[ks * 128];
                const uint32_t a0 = __float_as_uint(qv.x);
                const uint32_t a1 = __float_as_uint(qv.y);
                const uint32_t a2 = __float_as_uint(qv.z);
                const uint32_t a3 = __float_as_uint(qv.w);
#pragma unroll
                for (int ntp = 0; ntp < 4; ntp++) {
                    uint32_t b0a, b1a, b0b, b1b;
                    LDSM_X4(b0a, b1a, b0b, b1b,
                            Kad + (uint32_t)(ntp * 16 * AT_ROWB) + (uint32_t)(ks * 32));
                    MMA_TF32(s[2 * ntp],     a0, a1, a2, a3, b0a, b1a);
                    MMA_TF32(s[2 * ntp + 1], a0, a1, a2, a3, b0b, b1b);
                }
            }

            // ---- causal mask (only near the diagonal) ----
            if (k0 + 63 > qw0) {
                const int qlo = qw0 + r, qhi = qlo + 8;
#pragma unroll
                for (int nt = 0; nt < 8; nt++) {
                    const int key0 = k0 + nt * 8 + 2 * c;
                    if (key0     > qlo) s[nt][0] = NEG_BIG;
                    if (key0 + 1 > qlo) s[nt][1] = NEG_BIG;
                    if (key0     > qhi) s[nt][2] = NEG_BIG;
                    if (key0 + 1 > qhi) s[nt][3] = NEG_BIG;
                }
            }

            // ---- online softmax (exp2 domain) ----
            float cl = NEG_BIG, chv = NEG_BIG;
#pragma unroll
            for (int nt = 0; nt < 8; nt++) {
                cl  = fmaxf(cl,  fmaxf(s[nt][0], s[nt][1]));
                chv = fmaxf(chv, fmaxf(s[nt][2], s[nt][3]));
            }
            cl  = fmaxf(cl,  __shfl_xor_sync(0xffffffffu, cl, 1));
            cl  = fmaxf(cl,  __shfl_xor_sync(0xffffffffu, cl, 2));
            chv = fmaxf(chv, __shfl_xor_sync(0xffffffffu, chv, 1));
            chv = fmaxf(chv, __shfl_xor_sync(0xffffffffu, chv, 2));
            const float mn0 = fmaxf(m0v, cl), mn1 = fmaxf(m1v, chv);
            const float corr0 = exp2f(m0v - mn0), corr1 = exp2f(m1v - mn1);
            m0v = mn0; m1v = mn1;

            float sl = 0.f, sh = 0.f;
#pragma unroll
            for (int nt = 0; nt < 8; nt++) {
                s[nt][0] = exp2f(s[nt][0] - mn0); sl += s[nt][0];
                s[nt][1] = exp2f(s[nt][1] - mn0); sl += s[nt][1];
                s[nt][2] = exp2f(s[nt][2] - mn1); sh += s[nt][2];
                s[nt][3] = exp2f(s[nt][3] - mn1); sh += s[nt][3];
            }
            sl += __shfl_xor_sync(0xffffffffu, sl, 1);
            sl += __shfl_xor_sync(0xffffffffu, sl, 2);
            sh += __shfl_xor_sync(0xffffffffu, sh, 1);
            sh += __shfl_xor_sync(0xffffffffu, sh, 2);
            l0v = l0v * corr0 + sl;
            l1v = l1v * corr1 + sh;

#pragma unroll
            for (int nt = 0; nt < 8; nt++) {
                O[nt][0] *= corr0; O[nt][1] *= corr0;
                O[nt][2] *= corr1; O[nt][3] *= corr1;
                s[nt][0] = rna_tf32(s[nt][0]); s[nt][1] = rna_tf32(s[nt][1]);
                s[nt][2] = rna_tf32(s[nt][2]); s[nt][3] = rna_tf32(s[nt][3]);
            }

            // ---- O += P V : shuffle C->A frags; V B-frags via ldmatrix.x4 ----
#pragma unroll
            for (int ks = 0; ks < 8; ks++) {
                const float e0 = __shfl_sync(0xffffffffu, s[ks][0], l0p);
                const float o0 = __shfl_sync(0xffffffffu, s[ks][1], l0p);
                const float e2 = __shfl_sync(0xffffffffu, s[ks][0], l2p);
                const float o2 = __shfl_sync(0xffffffffu, s[ks][1], l2p);
                const float e1 = __shfl_sync(0xffffffffu, s[ks][2], l0p);
                const float o1 = __shfl_sync(0xffffffffu, s[ks][3], l0p);
                const float e3 = __shfl_sync(0xffffffffu, s[ks][2], l2p);
                const float o3 = __shfl_sync(0xffffffffu, s[ks][3], l2p);
                const uint32_t a0 = __float_as_uint(odd ? o0 : e0);
                const uint32_t a1 = __float_as_uint(odd ? o1 : e1);
                const uint32_t a2 = __float_as_uint(odd ? o2 : e2);
                const uint32_t a3 = __float_as_uint(odd ? o3 : e3);
#pragma unroll
                for (int ntp = 0; ntp < 4; ntp++) {
                    uint32_t b0a, b1a, b0b, b1b;
                    LDSM_X4(b0a, b1a, b0b, b1b,
                            Vad + (uint32_t)(ntp * 16 * AT_ROWB) + (uint32_t)(ks * 32));
                    MMA_TF32(O[2 * ntp],     a0, a1, a2, a3, b0a, b1a);
                    MMA_TF32(O[2 * ntp + 1], a0, a1, a2, a3, b0b, b1b);
                }
            }
        }
        __syncthreads();
    }

    // ---- epilogue: normalize, rna-round (feeds tf32 out-proj), store ----
    const float inv0 = 1.f / l0v, inv1 = 1.f / l1v;
    const size_t row0 = (size_t)(b * SS + qw0 + r);
#pragma unroll
    for (int nt = 0; nt < 8; nt++) {
        const int col = h * DHH + nt * 8 + 2 * c;
        float2 w0 = make_float2(rna_tf32(O[nt][0] * inv0), rna_tf32(O[nt][1] * inv0));
        float2 w1 = make_float2(rna_tf32(O[nt][2] * inv1), rna_tf32(O[nt][3] * inv1));
        *(float2*)&g_ctx[row0 * DDIM + col]       = w0;
        *(float2*)&g_ctx[(row0 + 8) * DDIM + col] = w1;
    }
#undef AT_ISSUE
}

// ===========================================================================
extern "C" void kernel_launch(void* const* d_in, const int* in_sizes, int n_in,
                              void* d_out, int out_size)
{
    (void)in_sizes; (void)n_in; (void)out_size;
    const float* x  = (const float*)d_in[0];
    const float* Wq = (const float*)d_in[1];
    const float* Wk = (const float*)d_in[2];
    const float* Wv = (const float*)d_in[3];
    const float* Wo = (const float*)d_in[4];
    const float* bo = (const float*)d_in[5];
    float* out = (float*)d_out;

    cudaFuncSetAttribute(qkv_mma_kernel, cudaFuncAttributeMaxDynamicSharedMemorySize,
                         GEMM_SMEM_BYTES);
    cudaFuncSetAttribute(out_mma_kernel, cudaFuncAttributeMaxDynamicSharedMemorySize,
                         GEMM_SMEM_BYTES);
    cudaFuncSetAttribute(attn_mma_kernel, cudaFuncAttributeMaxDynamicSharedMemorySize,
                         ATT_SMEM_BYTES);

    round_x_kernel<<<(MM * DDIM) / (256 * 4), 256>>>(x);
    transpose_round_kernel<<<dim3(32, 32, 4), dim3(32, 8)>>>(Wq, Wk, Wv, Wo);

    qkv_mma_kernel<<<dim3(DDIM / GTN, MM / GTM, 3), 256, GEMM_SMEM_BYTES>>>();

    attn_mma_kernel<<<dim3(SS / 128, BB * HH), 256, ATT_SMEM_BYTES>>>();

    out_mma_kernel<<<dim3(DDIM / GTN, MM / GTM), 256, GEMM_SMEM_BYTES>>>(bo, out);
}

// round 16
// speedup vs baseline: 1.1077x; 1.1077x over previous
#include <cuda_runtime.h>
#include <math.h>
#include <stdint.h>

// Problem constants
#define BB  2
#define SS  4096
#define DDIM 1024
#define HH  16
#define DHH 64
#define MM  (BB*SS)   // 8192 rows

// Scratch (allocation-free rule: __device__ globals)
__device__ float g_x[MM*DDIM];                 // tf32-rounded x
__device__ float g_Wt[4u*DDIM*DDIM];           // tf32-rounded W^T (q,k,v,o)
__device__ float g_Q[MM*DDIM];                 // tf32-rounded q
__device__ float g_K[MM*DDIM];                 // tf32-rounded k, d-cols pair-interleaved per 8
__device__ float g_V[MM*DDIM];                 // tf32-rounded V TRANSPOSED: [b][h][d][s],
                                               //   s pair-interleaved per 8-group
__device__ float g_ctx[MM*DDIM];               // tf32-rounded ctx

__device__ __forceinline__ float rna_tf32(float x) {
    uint32_t u;
    asm("cvt.rna.tf32.f32 %0, %1;" : "=r"(u) : "f"(x));
    return __uint_as_float(u);
}

__device__ __forceinline__ uint32_t smem_u32(const void* p) {
    uint32_t a;
    asm("{ .reg .u64 t; cvta.to.shared.u64 t, %1; cvt.u32.u64 %0, t; }"
        : "=r"(a) : "l"(p));
    return a;
}

__device__ __forceinline__ void cp_async16(uint32_t dst, const void* src) {
    asm volatile("cp.async.cg.shared.global [%0], [%1], 16;"
                 :: "r"(dst), "l"(src) : "memory");
}
#define CP_COMMIT() asm volatile("cp.async.commit_group;" ::: "memory")

#define MMA_TF32(c, a0, a1, a2, a3, b0, b1)                                    \
    asm volatile(                                                              \
        "mma.sync.aligned.m16n8k8.row.col.f32.tf32.tf32.f32 "                  \
        "{%0,%1,%2,%3},{%4,%5,%6,%7},{%8,%9},{%0,%1,%2,%3};"                   \
        : "+f"((c)[0]), "+f"((c)[1]), "+f"((c)[2]), "+f"((c)[3])               \
        : "r"(a0), "r"(a1), "r"(a2), "r"(a3), "r"(b0), "r"(b1))

#define LDSM_X4(r0, r1, r2, r3, addr)                                          \
    asm volatile("ldmatrix.sync.aligned.m8n8.x4.shared.b16 {%0,%1,%2,%3}, [%4];" \
                 : "=r"(r0), "=r"(r1), "=r"(r2), "=r"(r3) : "r"(addr))

#define LDSM_X2(r0, r1, addr)                                                  \
    asm volatile("ldmatrix.sync.aligned.m8n8.x2.shared.b16 {%0,%1}, [%2];"     \
                 : "=r"(r0), "=r"(r1) : "r"(addr))

// ===========================================================================
// Pre-pass kernels: tf32 RNA rounding of x; round+transpose for weights
// ===========================================================================
__global__ __launch_bounds__(256) void round_x_kernel(const float* __restrict__ x)
{
    const size_t i = ((size_t)blockIdx.x * 256 + threadIdx.x) * 4;
    float4 v = *(const float4*)(x + i);
    v.x = rna_tf32(v.x); v.y = rna_tf32(v.y);
    v.z = rna_tf32(v.z); v.w = rna_tf32(v.w);
    *(float4*)(g_x + i) = v;
}

__global__ __launch_bounds__(256) void transpose_round_kernel(
    const float* __restrict__ Wq, const float* __restrict__ Wk,
    const float* __restrict__ Wv, const float* __restrict__ Wo)
{
    __shared__ float t[32][33];
    const int z = blockIdx.z;
    const float* W = (z == 0) ? Wq : (z == 1) ? Wk : (z == 2) ? Wv : Wo;
    float* Wt = g_Wt + (size_t)z * DDIM * DDIM;
    const int x0 = blockIdx.x * 32, y0 = blockIdx.y * 32;
    const int tx = threadIdx.x, ty = threadIdx.y;   // block (32,8)
#pragma unroll
    for (int i = 0; i < 4; i++) {
        const int row = ty + i * 8;
        t[row][tx] = W[(size_t)(y0 + row) * DDIM + x0 + tx];
    }
    __syncthreads();
#pragma unroll
    for (int i = 0; i < 4; i++) {
        const int row = ty + i * 8;
        Wt[(size_t)(x0 + row) * DDIM + y0 + tx] = rna_tf32(t[tx][row]);
    }
}

// ===========================================================================
// tf32 mma.sync GEMM v2 (R13/R14 proven): C = A @ Bt^T, CTA 128x128, BK=32.
// cp.async direct staging + ldmatrix fragment loads. 2 CTAs/SM.
// perm_cols: d-cols pair-interleaved within 8-groups (for g_K).
// v_trans:   output TRANSPOSED to [b][h][d][s] with s pair-interleaved (g_V).
// ===========================================================================
#define GTM 128
#define GTN 128
#define GTK 32
#define GSTG_F 8192                            // A 4096 + B 4096 floats = 32KB
#define GEMM_SMEM_BYTES (3 * GSTG_F * 4)       // 98304; x2 CTAs = 192KB

__device__ __forceinline__ void gemm_mma_body(const float* __restrict__ A,
                                              const float* __restrict__ Bt,
                                              float* __restrict__ C,
                                              const float* __restrict__ bias,
                                              bool round_out, bool perm_cols,
                                              bool v_trans)
{
    extern __shared__ float sm[];
    const uint32_t sbase = smem_u32(sm);
    const int tid  = threadIdx.x;
    const int lane = tid & 31;
    const int warp = tid >> 5;
    const int wm   = warp >> 2;          // 0..1
    const int wn   = warp & 3;           // 0..3
    const int m0   = blockIdx.y * GTM;
    const int n0   = blockIdx.x * GTN;

    const int aro = lane & 15;
    const int akx = lane >> 4;
    const int bro = lane & 7;
    const int bkx = (lane >> 3) & 1;
    const int l7  = lane & 7;

    float acc[16][4];
#pragma unroll
    for (int t = 0; t < 16; t++)
#pragma unroll
        for (int e = 0; e < 4; e++) acc[t][e] = 0.f;

#define G_ISSUE(it, s)                                                          \
    {                                                                           \
        const int kc = (it) * GTK;                                              \
        const uint32_t st = sbase + (uint32_t)(s) * (GSTG_F * 4);               \
        _Pragma("unroll")                                                       \
        for (int t = 0; t < 4; t++) {                                           \
            const int ch = tid + t * 256;                                       \
            const int row = ch >> 3, ck = ch & 7;                               \
            const uint32_t doff = row * 128 + ((ck ^ (row & 7)) << 4);          \
            cp_async16(st + doff, A  + (size_t)(m0 + row) * DDIM + kc + ck * 4);\
            cp_async16(st + 16384 + doff,                                       \
                       Bt + (size_t)(n0 + row) * DDIM + kc + ck * 4);           \
        }                                                                       \
        CP_COMMIT();                                                            \
    }

    G_ISSUE(0, 0);
    G_ISSUE(1, 1);

    for (int it = 0; it < 32; ++it) {
        if (it < 31) asm volatile("cp.async.wait_group 1;" ::: "memory");
        else         asm volatile("cp.async.wait_group 0;" ::: "memory");
        __syncthreads();

        const uint32_t sA = sbase + (uint32_t)(it % 3) * (GSTG_F * 4);
        const uint32_t sB = sA + 16384;

#pragma unroll
        for (int ks = 0; ks < 4; ks++) {
            const uint32_t aoff = (uint32_t)(((2 * ks + akx) ^ l7) << 4);
            const uint32_t boff = (uint32_t)(((2 * ks + bkx) ^ l7) << 4);
            uint32_t af[4][4];
            uint32_t bf[4][2];
#pragma unroll
            for (int i = 0; i < 4; i++) {
                const uint32_t addr = sA + (wm * 64 + i * 16 + aro) * 128 + aoff;
                LDSM_X4(af[i][0], af[i][1], af[i][2], af[i][3], addr);
            }
#pragma unroll
            for (int j = 0; j < 4; j++) {
                const uint32_t addr = sB + (wn * 32 + j * 8 + bro) * 128 + boff;
                LDSM_X2(bf[j][0], bf[j][1], addr);
            }
#pragma unroll
            for (int i = 0; i < 4; i++)
#pragma unroll
                for (int j = 0; j < 4; j++)
                    MMA_TF32(acc[i * 4 + j],
                             af[i][0], af[i][1], af[i][2], af[i][3],
                             bf[j][0], bf[j][1]);
        }

        __syncthreads();
        if (it + 2 < 32) G_ISSUE(it + 2, (it + 2) % 3);
    }

    const int g   = lane >> 2;
    const int cth = lane & 3;
    const int p0  = (cth & 1) * 4 + (cth >> 1);      // K interleave pos of d=2*cth
    const int spos = 2 * (g & 3) + (g >> 2);         // V interleave pos of s-in-8
#pragma unroll
    for (int i = 0; i < 4; i++) {
        const int row = m0 + wm * 64 + i * 16 + g;
#pragma unroll
        for (int j = 0; j < 4; j++) {
            const int col = n0 + wn * 32 + j * 8 + cth * 2;
            float2 v0 = make_float2(acc[i * 4 + j][0], acc[i * 4 + j][1]);
            float2 v1 = make_float2(acc[i * 4 + j][2], acc[i * 4 + j][3]);
            if (bias != nullptr) {
                const float b0 = bias[col], b1 = bias[col + 1];
                v0.x += b0; v0.y += b1;
                v1.x += b0; v1.y += b1;
            }
            if (round_out) {
                v0.x = rna_tf32(v0.x); v0.y = rna_tf32(v0.y);
                v1.x = rna_tf32(v1.x); v1.y = rna_tf32(v1.y);
            }
            if (v_trans) {
                // Vt[((b*16+h)*64 + d)][s_t], s_t pair-interleaved per 8-group
                const int b_ = row >> 12, srow = row & 4095;
                const size_t s_t = (size_t)(srow & ~7) + spos;
                const int h_ = col >> 6, d0 = col & 63;
                float* vt = C + ((size_t)((b_ * HH + h_) * DHH + d0)) * SS;
                vt[s_t]          = v0.x;
                vt[SS + s_t]     = v0.y;   // d0+1
                vt[s_t + 8]      = v1.x;   // row+8 -> same pos, +8
                vt[SS + s_t + 8] = v1.y;
            } else if (perm_cols) {
                float* cp0 = &C[(size_t)row * DDIM + n0 + wn * 32 + j * 8];
                float* cp1 = cp0 + (size_t)8 * DDIM;
                cp0[p0] = v0.x; cp0[p0 + 2] = v0.y;
                cp1[p0] = v1.x; cp1[p0 + 2] = v1.y;
            } else {
                *(float2*)&C[(size_t)row * DDIM + col]       = v0;
                *(float2*)&C[(size_t)(row + 8) * DDIM + col] = v1;
            }
        }
    }
#undef G_ISSUE
}

__global__ __launch_bounds__(256, 2) void qkv_mma_kernel()
{
    const float* Bt = g_Wt + (size_t)blockIdx.z * DDIM * DDIM;
    float* Cp = (blockIdx.z == 0) ? g_Q : (blockIdx.z == 1) ? g_K : g_V;
    gemm_mma_body(g_x, Bt, Cp, nullptr, true, blockIdx.z == 1, blockIdx.z == 2);
}

__global__ __launch_bounds__(256, 2) void out_mma_kernel(const float* __restrict__ bo,
                                                         float* __restrict__ out)
{
    gemm_mma_body(g_ctx, g_Wt + 3ull * DDIM * DDIM, out, bo, false, false, false);
}

// ===========================================================================
// tf32 mma.sync causal flash attention — SHUFFLE-FREE PV.
// CTA: 128 queries x one (b,h), 256 threads (8 warps x 16 q-rows), 2 CTAs/SM.
// K staged with KEY-ROWS pair-interleaved per 8-group (staging-time index
// permute: staged row p holds logical key (p&1)*4 + (p>>1)); d-columns keep
// the R12 pair-interleave -> K B-frag = one LDS.64. S C-frag position (r,2c)
// is then LOGICAL key c, so the PV A-frag is a pure register relabel
// (s0,s2,s1,s3) -- zero shuffles. V transposed [d][s] with s pair-interleaved
// (R14): V B-frag = one LDS.64 whose (2c,2c+1) = logical keys (c, c+4).
// Q A-frags in smem, scaled by 0.125*log2(e), rna'd after scaling.
// exp2-domain softmax.
// ===========================================================================
#define NEG_BIG   (-1e30f)
#define QK_SCALE  0.18033688f              // 0.125 * log2(e)
#define AT_STRIDE 72
#define AT_ROWB   (AT_STRIDE * 4)           // 288 bytes per staged row
#define AT_TILE_F (64 * AT_STRIDE)          // 4608 floats (18432 B)
#define AT_STAGE_F (2 * AT_TILE_F)          // K + V per stage = 9216 floats
#define QF_FLOATS 8192                      // 8 warps x 8 ks x 32 lanes x 4
#define ATT_SMEM_BYTES ((QF_FLOATS + 2 * AT_STAGE_F) * 4)   // 106496

__global__ __launch_bounds__(256, 2) void attn_mma_kernel()
{
    extern __shared__ float smf[];
    const uint32_t sb  = smem_u32(smf);
    const uint32_t kvb = sb + QF_FLOATS * 4;          // KV staging base
    float* kvf = smf + QF_FLOATS;
    const int tid = threadIdx.x, lane = tid & 31, warp = tid >> 5;
    const int bh = blockIdx.y, b = bh >> 4, h = bh & 15;
    const int qt = (int)gridDim.x - 1 - (int)blockIdx.x;   // heavy first
    const int q0 = qt * 128;
    const int qw0 = q0 + warp * 16;
    const int nb = 2 * qt + 2;
    const int r = lane >> 2, c = lane & 3;

    const float* gq  = g_Q + (size_t)(b * SS + q0) * DDIM + h * DHH;
    const float* gk0 = g_K + (size_t)(b * SS) * DDIM + h * DHH;
    const float* gvt = g_V + (size_t)((b * HH + h) * DHH) * SS;   // [d][s]

    // ---- stage Q (128 x 64, stride 72) into KV region, build Q-frags ----
#pragma unroll
    for (int i = 0; i < 8; i++) {
        const int ch = tid + i * 256;
        const int row = ch >> 4, c16 = ch & 15;
        cp_async16(kvb + row * AT_ROWB + c16 * 16, gq + (size_t)row * DDIM + c16 * 4);
    }
    CP_COMMIT();
    asm volatile("cp.async.wait_group 0;" ::: "memory");
    __syncthreads();

    {
        float* qfw = smf + warp * 1024 + lane * 4;
#pragma unroll
        for (int ks = 0; ks < 8; ks++) {
            const float* qs = kvf + (warp * 16 + r) * AT_STRIDE + ks * 8 + c;
            float4 qv = make_float4(rna_tf32(qs[0] * QK_SCALE),
                                    rna_tf32(qs[8 * AT_STRIDE] * QK_SCALE),
                                    rna_tf32(qs[4] * QK_SCALE),
                                    rna_tf32(qs[8 * AT_STRIDE + 4] * QK_SCALE));
            *(float4*)&qfw[ks * 128] = qv;
        }
    }
    __syncthreads();

    float O[8][4];
#pragma unroll
    for (int t = 0; t < 8; t++)
#pragma unroll
        for (int e = 0; e < 4; e++) O[t][e] = 0.f;
    float m0v = NEG_BIG, m1v = NEG_BIG, l0v = 0.f, l1v = 0.f;

    // K staging: staged row p <- logical key (p&~7) | ((p&1)<<2) | ((p&7)>>1).
    // V tile rows = d (16 chunks of interleaved s each).
#define AT_ISSUE(kb, s)                                                            \
    {                                                                              \
        const float* gk = gk0 + (size_t)(kb) * 64 * DDIM;                          \
        const float* gv = gvt + (size_t)(kb) * 64;                                 \
        const uint32_t db = kvb + (uint32_t)(s) * (AT_STAGE_F * 4);                \
        _Pragma("unroll")                                                          \
        for (int i = 0; i < 4; i++) {                                              \
            const int ch = tid + i * 256;                                          \
            const int row = ch >> 4, c16 = ch & 15;                                \
            const int src = (row & ~7) | (((row & 1) << 2) | ((row & 7) >> 1));    \
            cp_async16(db + row * AT_ROWB + c16 * 16,                              \
                       gk + (size_t)src * DDIM + c16 * 4);                         \
            cp_async16(db + (AT_TILE_F * 4) + row * AT_ROWB + c16 * 16,            \
                       gv + (size_t)row * SS + c16 * 4);                           \
        }                                                                          \
    }

    AT_ISSUE(0, 0);
    CP_COMMIT();

    const float* qfw = smf + warp * 1024 + lane * 4;

    for (int kb = 0; kb < nb; kb++) {
        if (kb + 1 < nb) {
            AT_ISSUE(kb + 1, (kb + 1) & 1);
            CP_COMMIT();
            asm volatile("cp.async.wait_group 1;" ::: "memory");
        } else {
            asm volatile("cp.async.wait_group 0;" ::: "memory");
        }
        __syncthreads();

        const int k0 = kb * 64;
        if (k0 <= qw0 + 15) {                       // else fully masked: skip
            const float* Ksm = kvf + (kb & 1) * AT_STAGE_F;
            const float* Vsm = Ksm + AT_TILE_F;

            // ---- S = Q K^T (K: LDS.64 B-frags; key rows permuted) ----
            float s[8][4];
#pragma unroll
            for (int t = 0; t < 8; t++)
#pragma unroll
                for (int e = 0; e < 4; e++) s[t][e] = 0.f;

#pragma unroll
            for (int ks = 0; ks < 8; ks++) {
                const float4 qv = *(const float4*)&qfw[ks * 128];
                const uint32_t a0 = __float_as_uint(qv.x);
                const uint32_t a1 = __float_as_uint(qv.y);
                const uint32_t a2 = __float_as_uint(qv.z);
                const uint32_t a3 = __float_as_uint(qv.w);
#pragma unroll
                for (int nt = 0; nt < 8; nt++) {
                    const float2 kf = *(const float2*)(Ksm + (nt * 8 + r) * AT_STRIDE
                                                       + ks * 8 + 2 * c);
                    MMA_TF32(s[nt], a0, a1, a2, a3,
                             __float_as_uint(kf.x), __float_as_uint(kf.y));
                }
            }

            // ---- causal mask (logical keys: s0/s2 -> c, s1/s3 -> c+4) ----
            if (k0 + 63 > qw0) {
                const int qlo = qw0 + r, qhi = qlo + 8;
#pragma unroll
                for (int nt = 0; nt < 8; nt++) {
                    const int key0 = k0 + nt * 8 + c;     // logical key of slot 0/2
                    const int key1 = key0 + 4;            // logical key of slot 1/3
                    if (key0 > qlo) s[nt][0] = NEG_BIG;
                    if (key1 > qlo) s[nt][1] = NEG_BIG;
                    if (key0 > qhi) s[nt][2] = NEG_BIG;
                    if (key1 > qhi) s[nt][3] = NEG_BIG;
                }
            }

            // ---- online softmax (exp2 domain) ----
            float cl = NEG_BIG, chv = NEG_BIG;
#pragma unroll
            for (int nt = 0; nt < 8; nt++) {
                cl  = fmaxf(cl,  fmaxf(s[nt][0], s[nt][1]));
                chv = fmaxf(chv, fmaxf(s[nt][2], s[nt][3]));
            }
            cl  = fmaxf(cl,  __shfl_xor_sync(0xffffffffu, cl, 1));
            cl  = fmaxf(cl,  __shfl_xor_sync(0xffffffffu, cl, 2));
            chv = fmaxf(chv, __shfl_xor_sync(0xffffffffu, chv, 1));
            chv = fmaxf(chv, __shfl_xor_sync(0xffffffffu, chv, 2));
            const float mn0 = fmaxf(m0v, cl), mn1 = fmaxf(m1v, chv);
            const float corr0 = exp2f(m0v - mn0), corr1 = exp2f(m1v - mn1);
            m0v = mn0; m1v = mn1;

            float sl = 0.f, sh = 0.f;
#pragma unroll
            for (int nt = 0; nt < 8; nt++) {
                s[nt][0] = exp2f(s[nt][0] - mn0); sl += s[nt][0];
                s[nt][1] = exp2f(s[nt][1] - mn0); sl += s[nt][1];
                s[nt][2] = exp2f(s[nt][2] - mn1); sh += s[nt][2];
                s[nt][3] = exp2f(s[nt][3] - mn1); sh += s[nt][3];
            }
            sl += __shfl_xor_sync(0xffffffffu, sl, 1);
            sl += __shfl_xor_sync(0xffffffffu, sl, 2);
            sh += __shfl_xor_sync(0xffffffffu, sh, 1);
            sh += __shfl_xor_sync(0xffffffffu, sh, 2);
            l0v = l0v * corr0 + sl;
            l1v = l1v * corr1 + sh;

#pragma unroll
            for (int nt = 0; nt < 8; nt++) {
                O[nt][0] *= corr0; O[nt][1] *= corr0;
                O[nt][2] *= corr1; O[nt][3] *= corr1;
                s[nt][0] = rna_tf32(s[nt][0]); s[nt][1] = rna_tf32(s[nt][1]);
                s[nt][2] = rna_tf32(s[nt][2]); s[nt][3] = rna_tf32(s[nt][3]);
            }

            // ---- O += P V : A-frag = register relabel (NO shuffles);
            //      V B-frag = one LDS.64 (interleaved s = logical keys c,c+4) ----
#pragma unroll
            for (int ks = 0; ks < 8; ks++) {
                const uint32_t a0 = __float_as_uint(s[ks][0]);   // (q=r,   key c)
                const uint32_t a1 = __float_as_uint(s[ks][2]);   // (q=r+8, key c)
                const uint32_t a2 = __float_as_uint(s[ks][1]);   // (q=r,   key c+4)
                const uint32_t a3 = __float_as_uint(s[ks][3]);   // (q=r+8, key c+4)
#pragma unroll
                for (int nt = 0; nt < 8; nt++) {
                    const float2 vf = *(const float2*)(Vsm + (nt * 8 + r) * AT_STRIDE
                                                       + ks * 8 + 2 * c);
                    MMA_TF32(O[nt], a0, a1, a2, a3,
                             __float_as_uint(vf.x), __float_as_uint(vf.y));
                }
            }
        }
        __syncthreads();
    }

    // ---- epilogue: normalize, rna-round (feeds tf32 out-proj), store ----
    const float inv0 = 1.f / l0v, inv1 = 1.f / l1v;
    const size_t row0 = (size_t)(b * SS + qw0 + r);
#pragma unroll
    for (int nt = 0; nt < 8; nt++) {
        const int col = h * DHH + nt * 8 + 2 * c;
        float2 w0 = make_float2(rna_tf32(O[nt][0] * inv0), rna_tf32(O[nt][1] * inv0));
        float2 w1 = make_float2(rna_tf32(O[nt][2] * inv1), rna_tf32(O[nt][3] * inv1));
        *(float2*)&g_ctx[row0 * DDIM + col]       = w0;
        *(float2*)&g_ctx[(row0 + 8) * DDIM + col] = w1;
    }
#undef AT_ISSUE
}

// ===========================================================================
extern "C" void kernel_launch(void* const* d_in, const int* in_sizes, int n_in,
                              void* d_out, int out_size)
{
    (void)in_sizes; (void)n_in; (void)out_size;
    const float* x  = (const float*)d_in[0];
    const float* Wq = (const float*)d_in[1];
    const float* Wk = (const float*)d_in[2];
    const float* Wv = (const float*)d_in[3];
    const float* Wo = (const float*)d_in[4];
    const float* bo = (const float*)d_in[5];
    float* out = (float*)d_out;

    cudaFuncSetAttribute(qkv_mma_kernel, cudaFuncAttributeMaxDynamicSharedMemorySize,
                         GEMM_SMEM_BYTES);
    cudaFuncSetAttribute(out_mma_kernel, cudaFuncAttributeMaxDynamicSharedMemorySize,
                         GEMM_SMEM_BYTES);
    cudaFuncSetAttribute(attn_mma_kernel, cudaFuncAttributeMaxDynamicSharedMemorySize,
                         ATT_SMEM_BYTES);

    round_x_kernel<<<(MM * DDIM) / (256 * 4), 256>>>(x);
    transpose_round_kernel<<<dim3(32, 32, 4), dim3(32, 8)>>>(Wq, Wk, Wv, Wo);

    qkv_mma_kernel<<<dim3(DDIM / GTN, MM / GTM, 3), 256, GEMM_SMEM_BYTES>>>();

    attn_mma_kernel<<<dim3(SS / 128, BB * HH), 256, ATT_SMEM_BYTES>>>();

    out_mma_kernel<<<dim3(DDIM / GTN, MM / GTM), 256, GEMM_SMEM_BYTES>>>(bo, out);
}